// round 1
// baseline (speedup 1.0000x reference)
#include <cuda_runtime.h>
#include <cuda_bf16.h>
#include <math.h>

#define T_   16384
#define D_   1024
#define E_   8
#define K_   2
#define H_   2048
#define BSD  (T_ * D_)          // 16777216
#define NBLK 64                 // token blocks of 256 (64*256 = 16384)
#define MAXCH 520               // max 64-row chunks: 32768/64 + 8 partials
#define MAXROWS (T_ * K_ + E_ * 64)   // 33280 padded rows

// ---------------- device scratch (static; no allocations) ----------------
__device__ float g_yall[(size_t)MAXROWS * D_];    // gathered, pre-scaled tokens
__device__ float g_partial[(size_t)MAXCH * H_];   // per-chunk colsum partials
__device__ float g_probs[T_ * E_];
__device__ int   g_ce[T_ * K_];
__device__ float g_cw[T_ * K_];
__device__ int   g_rank[T_ * K_];
__device__ int   g_blockcnt[NBLK][E_];
__device__ int   g_blockbase[NBLK][E_];
__device__ int   g_cnt[E_];
__device__ int   g_poff[E_ + 1];
__device__ int   g_chunk_expert[MAXCH];
__device__ int   g_chunk_row0[MAXCH];
__device__ int   g_chunk_start[E_];
__device__ int   g_chunk_cnt[E_];
__device__ int   g_nchunks;
__device__ int   g_row_token[MAXROWS];
__device__ float g_row_w[MAXROWS];
__device__ float g_acc[E_ * H_];
__device__ float g_psum[E_];

// ---------------- packed f32x2 helpers (sm_103a FFMA2) ----------------
#define FMA_F32X2(d, a, b) \
    asm volatile("fma.rn.f32x2 %0, %1, %2, %0;" : "+l"(d) : "l"(a), "l"(b))

__device__ __forceinline__ unsigned long long dup_f32x2(float a) {
    unsigned long long r;
    unsigned ai = __float_as_uint(a);
    asm("mov.b64 %0, {%1, %1};" : "=l"(r) : "r"(ai));
    return r;
}
__device__ __forceinline__ void unpack_f32x2(unsigned long long v, float& lo, float& hi) {
    unsigned l, h;
    asm("mov.b64 {%0, %1}, %2;" : "=r"(l), "=r"(h) : "l"(v));
    lo = __uint_as_float(l);
    hi = __uint_as_float(h);
}

// ---------------- kernels ----------------

__global__ void k_zero(float* out, int n) {
    int i = blockIdx.x * blockDim.x + threadIdx.x;
    int stride = gridDim.x * blockDim.x;
    for (; i < n; i += stride) out[i] = 0.0f;
}

// One block per token: 8 warps compute the 8 gate logits; thread 0 does top-2 +
// softmaxes and writes routing choices + full probs (for aux p_i).
__global__ void __launch_bounds__(256) k_gate(const float* __restrict__ x,
                                              const float* __restrict__ gw) {
    int t = blockIdx.x;
    __shared__ float xs[D_];
    __shared__ float lg[E_];
    const float* xr = x + (size_t)t * D_;
    for (int i = threadIdx.x; i < D_; i += 256) xs[i] = xr[i];
    __syncthreads();
    int w = threadIdx.x >> 5, lane = threadIdx.x & 31;
    float s = 0.0f;
    #pragma unroll 8
    for (int i = 0; i < D_ / 32; i++) {
        int d = i * 32 + lane;
        s += xs[d] * gw[d * E_ + w];
    }
    #pragma unroll
    for (int o = 16; o; o >>= 1) s += __shfl_xor_sync(0xffffffffu, s, o);
    if (lane == 0) lg[w] = s;
    __syncthreads();
    if (threadIdx.x == 0) {
        int i0 = 0; float v0 = lg[0];
        #pragma unroll
        for (int e = 1; e < E_; e++) if (lg[e] > v0) { v0 = lg[e]; i0 = e; }
        int i1 = -1; float v1 = -1e30f;
        #pragma unroll
        for (int e = 0; e < E_; e++) if (e != i0 && lg[e] > v1) { v1 = lg[e]; i1 = e; }
        float ee = expf(v1 - v0);
        float w0 = 1.0f / (1.0f + ee);
        float w1 = ee / (1.0f + ee);
        g_ce[t * 2 + 0] = i0; g_ce[t * 2 + 1] = i1;
        g_cw[t * 2 + 0] = w0; g_cw[t * 2 + 1] = w1;
        float ssum = 0.0f, pe[E_];
        #pragma unroll
        for (int e = 0; e < E_; e++) { pe[e] = expf(lg[e] - v0); ssum += pe[e]; }
        float inv = 1.0f / ssum;
        #pragma unroll
        for (int e = 0; e < E_; e++) g_probs[t * E_ + e] = pe[e] * inv;
    }
}

// Deterministic per-block ranks (token order) + per-block expert counts.
__global__ void __launch_bounds__(256) k_count() {
    int b = blockIdx.x, i = threadIdx.x, t = b * 256 + i;
    __shared__ short se0[256], se1[256];
    __shared__ int cnt[E_];
    int e0 = g_ce[t * 2], e1 = g_ce[t * 2 + 1];
    se0[i] = (short)e0; se1[i] = (short)e1;
    if (i < E_) cnt[i] = 0;
    __syncthreads();
    int r0 = 0, r1 = 0;
    for (int j = 0; j < i; j++) {
        r0 += (se0[j] == e0) + (se1[j] == e0);
        r1 += (se0[j] == e1) + (se1[j] == e1);
    }
    g_rank[t * 2] = r0; g_rank[t * 2 + 1] = r1;
    atomicAdd(&cnt[e0], 1); atomicAdd(&cnt[e1], 1);
    __syncthreads();
    if (i < E_) g_blockcnt[b][i] = cnt[i];
}

// Prefix scan over blocks per expert; padded offsets; 64-row chunk map.
__global__ void k_scan() {
    int e = threadIdx.x;
    __shared__ int nc_s[E_];
    if (e < E_) {
        int c = 0;
        #pragma unroll 8
        for (int b = 0; b < NBLK; b++) { g_blockbase[b][e] = c; c += g_blockcnt[b][e]; }
        g_cnt[e] = c;
        nc_s[e] = (c + 63) >> 6;
    }
    __syncthreads();
    if (threadIdx.x == 0) {
        int poff = 0, nch = 0;
        for (int ee = 0; ee < E_; ee++) {
            g_poff[ee] = poff;
            g_chunk_start[ee] = nch;
            int nc = nc_s[ee];
            g_chunk_cnt[ee] = nc;
            for (int cc = 0; cc < nc; cc++) {
                g_chunk_expert[nch] = ee;
                g_chunk_row0[nch] = poff + cc * 64;
                nch++;
            }
            poff += nc * 64;
        }
        g_poff[E_] = poff;
        g_nchunks = nch;
    }
}

// Per-token global row assignment.
__global__ void __launch_bounds__(256) k_rows() {
    int t = blockIdx.x * 256 + threadIdx.x;
    int blk = blockIdx.x;
    #pragma unroll
    for (int k = 0; k < K_; k++) {
        int e = g_ce[t * 2 + k];
        int row = g_poff[e] + g_blockbase[blk][e] + g_rank[t * 2 + k];
        g_row_token[row] = t;
        g_row_w[row] = g_cw[t * 2 + k];
    }
}

// Gather scaled token rows into packed per-expert layout; zero pad rows.
__global__ void __launch_bounds__(256) k_gather(const float* __restrict__ x) {
    int padtot = g_poff[E_];
    for (int rr = 0; rr < 16; rr++) {
        int row = blockIdx.x * 16 + rr;
        if (row >= padtot) return;
        int e = 0;
        #pragma unroll
        for (int ee = 0; ee < E_ - 1; ee++) if (row >= g_poff[ee + 1]) e = ee + 1;
        int local = row - g_poff[e];
        float4* dst = (float4*)(g_yall + (size_t)row * D_);
        if (local < g_cnt[e]) {
            int t = g_row_token[row];
            float w = g_row_w[row];
            const float4* src = (const float4*)(x + (size_t)t * D_);
            for (int i = threadIdx.x; i < D_ / 4; i += 256) {
                float4 v = src[i];
                v.x *= w; v.y *= w; v.z *= w; v.w *= w;
                dst[i] = v;
            }
        } else {
            float4 z = {0.f, 0.f, 0.f, 0.f};
            for (int i = threadIdx.x; i < D_ / 4; i += 256) dst[i] = z;
        }
    }
}

// Expert GEMM: per (chunk of 64 rows, 64-col H tile), compute gate & up
// projections with packed f32x2 FMAs, apply silu*up, column-sum over the 64
// rows, write deterministic per-chunk partials. 128 threads, 8x4 thread tile.
__global__ void __launch_bounds__(128) k_gemm(const float* __restrict__ wg,
                                              const float* __restrict__ wu) {
    int chunk = blockIdx.x;
    if (chunk >= g_nchunks) return;
    int htile = blockIdx.y;
    int e = g_chunk_expert[chunk];
    int row0 = g_chunk_row0[chunk];
    int h0 = htile * 64;

    const float* A = g_yall + (size_t)row0 * D_;
    const float* G = wg + (size_t)e * D_ * H_ + h0;
    const float* U = wu + (size_t)e * D_ * H_ + h0;

    __shared__ float As[16][68];   // k-major, padded stride (bank-friendly)
    __shared__ float Gs[16][64];
    __shared__ float Us[16][64];
    __shared__ float red[8][64];

    int tid = threadIdx.x;
    int tx = tid & 15;            // h group: cols tx*4 .. tx*4+3
    int ty = tid >> 4;            // token group: rows ty*8 .. ty*8+7
    int ar = tid >> 1, ac = (tid & 1) * 8;   // A load: row ar, cols ac..ac+7
    int bd = tid >> 3, bh = (tid & 7) * 8;   // B load: d-row bd, cols bh..bh+7

    unsigned long long accg[8][2] = {};
    unsigned long long accu[8][2] = {};

    for (int dk = 0; dk < D_; dk += 16) {
        float4 a0 = *(const float4*)(A + (size_t)ar * D_ + dk + ac);
        float4 a1 = *(const float4*)(A + (size_t)ar * D_ + dk + ac + 4);
        float4 gv0 = *(const float4*)(G + (size_t)(dk + bd) * H_ + bh);
        float4 gv1 = *(const float4*)(G + (size_t)(dk + bd) * H_ + bh + 4);
        float4 uv0 = *(const float4*)(U + (size_t)(dk + bd) * H_ + bh);
        float4 uv1 = *(const float4*)(U + (size_t)(dk + bd) * H_ + bh + 4);
        __syncthreads();
        As[ac + 0][ar] = a0.x; As[ac + 1][ar] = a0.y;
        As[ac + 2][ar] = a0.z; As[ac + 3][ar] = a0.w;
        As[ac + 4][ar] = a1.x; As[ac + 5][ar] = a1.y;
        As[ac + 6][ar] = a1.z; As[ac + 7][ar] = a1.w;
        *(float4*)&Gs[bd][bh] = gv0; *(float4*)&Gs[bd][bh + 4] = gv1;
        *(float4*)&Us[bd][bh] = uv0; *(float4*)&Us[bd][bh + 4] = uv1;
        __syncthreads();
        #pragma unroll
        for (int k = 0; k < 16; k++) {
            float4 am0 = *(const float4*)&As[k][ty * 8];
            float4 am1 = *(const float4*)&As[k][ty * 8 + 4];
            ulonglong2 gp = *(const ulonglong2*)&Gs[k][tx * 4];
            ulonglong2 up = *(const ulonglong2*)&Us[k][tx * 4];
            float a[8] = {am0.x, am0.y, am0.z, am0.w, am1.x, am1.y, am1.z, am1.w};
            #pragma unroll
            for (int i = 0; i < 8; i++) {
                unsigned long long ad = dup_f32x2(a[i]);
                FMA_F32X2(accg[i][0], ad, gp.x);
                FMA_F32X2(accg[i][1], ad, gp.y);
                FMA_F32X2(accu[i][0], ad, up.x);
                FMA_F32X2(accu[i][1], ad, up.y);
            }
        }
    }

    // epilogue: silu(gate)*up, sum over this thread's 8 token rows
    float cs[4] = {0.f, 0.f, 0.f, 0.f};
    #pragma unroll
    for (int i = 0; i < 8; i++) {
        #pragma unroll
        for (int p = 0; p < 2; p++) {
            float g0, g1, u0, u1;
            unpack_f32x2(accg[i][p], g0, g1);
            unpack_f32x2(accu[i][p], u0, u1);
            cs[p * 2 + 0] += (g0 / (1.0f + expf(-g0))) * u0;
            cs[p * 2 + 1] += (g1 / (1.0f + expf(-g1))) * u1;
        }
    }
    __syncthreads();
    #pragma unroll
    for (int j = 0; j < 4; j++) red[ty][tx * 4 + j] = cs[j];
    __syncthreads();
    #pragma unroll
    for (int s = 4; s > 0; s >>= 1) {
        if (ty < s) {
            #pragma unroll
            for (int j = 0; j < 4; j++)
                red[ty][tx * 4 + j] += red[ty + s][tx * 4 + j];
        }
        __syncthreads();
    }
    if (ty == 0) {
        #pragma unroll
        for (int j = 0; j < 4; j++)
            g_partial[(size_t)chunk * H_ + h0 + tx * 4 + j] = red[0][tx * 4 + j];
    }
}

// Deterministic reduction of chunk partials into per-expert accumulators.
__global__ void __launch_bounds__(256) k_colreduce() {
    int e = blockIdx.y;
    int h = blockIdx.x * 256 + threadIdx.x;
    int cs = g_chunk_start[e], cc = g_chunk_cnt[e];
    float s = 0.0f;
    for (int c = 0; c < cc; c++) s += g_partial[(size_t)(cs + c) * H_ + h];
    g_acc[e * H_ + h] = s;
}

// Deterministic p_i sum per expert.
__global__ void __launch_bounds__(256) k_psum() {
    int e = blockIdx.x;
    __shared__ float sm[256];
    float s = 0.0f;
    for (int t = threadIdx.x; t < T_; t += 256) s += g_probs[t * E_ + e];
    sm[threadIdx.x] = s;
    __syncthreads();
    for (int st = 128; st > 0; st >>= 1) {
        if (threadIdx.x < st) sm[threadIdx.x] += sm[threadIdx.x + st];
        __syncthreads();
    }
    if (threadIdx.x == 0) g_psum[e] = sm[0];
}

// Down projection: out[e, :] = acc[e] @ w_down[e]; plus aux loss scalar.
__global__ void __launch_bounds__(256) k_down(const float* __restrict__ wd,
                                              float* __restrict__ out,
                                              int out_size) {
    int e = blockIdx.y;
    int d = blockIdx.x * 256 + threadIdx.x;
    __shared__ float as[H_];
    for (int i = threadIdx.x; i < H_; i += 256) as[i] = g_acc[e * H_ + i];
    __syncthreads();
    const float* W = wd + (size_t)e * H_ * D_ + d;
    float s = 0.0f;
    #pragma unroll 8
    for (int h = 0; h < H_; h++) s += as[h] * W[(size_t)h * D_];
    out[e * D_ + d] = s;
    if (e == 0 && blockIdx.x == 0 && threadIdx.x == 0 && out_size > BSD) {
        float aux = 0.0f;
        #pragma unroll
        for (int ee = 0; ee < E_; ee++)
            aux += ((float)g_cnt[ee] / (float)T_) * (g_psum[ee] / (float)T_);
        out[BSD] = aux * (float)(E_ * E_);
    }
}

// ---------------- launch ----------------
extern "C" void kernel_launch(void* const* d_in, const int* in_sizes, int n_in,
                              void* d_out, int out_size) {
    const float* x  = (const float*)d_in[0];
    const float* gw = (const float*)d_in[1];
    const float* wg = (const float*)d_in[2];
    const float* wu = (const float*)d_in[3];
    const float* wd = (const float*)d_in[4];
    float* out = (float*)d_out;

    k_zero<<<2048, 256>>>(out, out_size);
    k_gate<<<T_, 256>>>(x, gw);
    k_count<<<NBLK, 256>>>();
    k_scan<<<1, 32>>>();
    k_rows<<<NBLK, 256>>>();
    k_gather<<<MAXROWS / 16, 256>>>(x);
    dim3 gg(MAXCH, H_ / 64);
    k_gemm<<<gg, 128>>>(wg, wu);
    dim3 gr(H_ / 256, E_);
    k_colreduce<<<gr, 256>>>();
    k_psum<<<E_, 256>>>();
    dim3 gd(D_ / 256, E_);
    k_down<<<gd, 256>>>(wd, out, out_size);
}

// round 7
// speedup vs baseline: 3.5667x; 3.5667x over previous
#include <cuda_runtime.h>
#include <cuda_bf16.h>
#include <cstdint>
#include <math.h>

#define T_   16384
#define D_   1024
#define E_   8
#define K_   2
#define H_   2048
#define BSD  (T_ * D_)
#define NBLK 64
#define CHROWS 128
#define MAXCH  264                          // 32768/128 + 8
#define MAXROWS (T_ * K_ + E_ * CHROWS)     // 33792

// ---------------- device scratch ----------------
__device__ float g_yall[(size_t)MAXROWS * D_];   // gathered, scaled, tf32-rounded
__device__ float g_wgt[(size_t)E_ * H_ * D_];    // w_gate^T [E][H][D], tf32
__device__ float g_wut[(size_t)E_ * H_ * D_];    // w_up^T   [E][H][D], tf32
__device__ float g_partial[(size_t)MAXCH * H_];
__device__ float g_probs[T_ * E_];
__device__ int   g_ce[T_ * K_];
__device__ float g_cw[T_ * K_];
__device__ int   g_rank[T_ * K_];
__device__ int   g_blockcnt[NBLK][E_];
__device__ int   g_blockbase[NBLK][E_];
__device__ int   g_cnt[E_];
__device__ int   g_poff[E_ + 1];
__device__ int   g_chunk_expert[MAXCH];
__device__ int   g_chunk_row0[MAXCH];
__device__ int   g_chstart[E_];
__device__ int   g_chcnt[E_];
__device__ int   g_nchunks;
__device__ int   g_row_token[MAXROWS];
__device__ float g_row_w[MAXROWS];
__device__ float g_acc[E_ * H_];
__device__ float g_psum[E_];

// ---------------- helpers ----------------
__device__ __forceinline__ float to_tf32(float x) {
    float r;
    asm("cvt.rna.tf32.f32 %0, %1;" : "=f"(r) : "f"(x));
    return r;
}
__device__ __forceinline__ uint32_t smem_u32(const void* p) {
    uint32_t a;
    asm("{ .reg .u64 t; cvta.to.shared.u64 t, %1; cvt.u32.u64 %0, t; }" : "=r"(a) : "l"(p));
    return a;
}
__device__ __forceinline__ void cpa16(uint32_t dst, const void* src) {
    asm volatile("cp.async.cg.shared.global [%0], [%1], 16;" :: "r"(dst), "l"(src) : "memory");
}
#define CP_COMMIT() asm volatile("cp.async.commit_group;" ::: "memory")
#define CP_WAIT0()  asm volatile("cp.async.wait_group 0;" ::: "memory")

__device__ __forceinline__ void mma8(float* c, const float* a, const float* b) {
    asm volatile(
        "mma.sync.aligned.m16n8k8.row.col.f32.tf32.tf32.f32 "
        "{%0,%1,%2,%3}, {%4,%5,%6,%7}, {%8,%9}, {%0,%1,%2,%3};"
        : "+f"(c[0]), "+f"(c[1]), "+f"(c[2]), "+f"(c[3])
        : "r"(__float_as_uint(a[0])), "r"(__float_as_uint(a[1])),
          "r"(__float_as_uint(a[2])), "r"(__float_as_uint(a[3])),
          "r"(__float_as_uint(b[0])), "r"(__float_as_uint(b[1])));
}

// ---------------- setup kernels ----------------
__global__ void k_zero(float* out, int n) {
    int i = blockIdx.x * blockDim.x + threadIdx.x;
    for (; i < n; i += gridDim.x * blockDim.x) out[i] = 0.0f;
}

__global__ void __launch_bounds__(256) k_transpose(const float* __restrict__ wg,
                                                   const float* __restrict__ wu) {
    int e = blockIdx.z & 7, mat = blockIdx.z >> 3;
    const float* src = (mat ? wu : wg) + (size_t)e * D_ * H_;
    float* dst = (mat ? g_wut : g_wgt) + (size_t)e * H_ * D_;
    __shared__ float t[32][33];
    int d0 = blockIdx.x * 32, h0 = blockIdx.y * 32;
    int tx = threadIdx.x & 31, ty = threadIdx.x >> 5;
    #pragma unroll
    for (int r = 0; r < 4; r++) {
        int row = ty + r * 8;
        t[row][tx] = src[(size_t)(d0 + row) * H_ + h0 + tx];
    }
    __syncthreads();
    #pragma unroll
    for (int r = 0; r < 4; r++) {
        int row = ty + r * 8;
        dst[(size_t)(h0 + row) * D_ + d0 + tx] = to_tf32(t[tx][row]);
    }
}

__global__ void __launch_bounds__(256) k_gate(const float* __restrict__ x,
                                              const float* __restrict__ gw) {
    int t = blockIdx.x;
    __shared__ float xs[D_];
    __shared__ float lg[E_];
    const float* xr = x + (size_t)t * D_;
    for (int i = threadIdx.x; i < D_; i += 256) xs[i] = xr[i];
    __syncthreads();
    int w = threadIdx.x >> 5, lane = threadIdx.x & 31;
    float s = 0.0f;
    #pragma unroll 8
    for (int i = 0; i < D_ / 32; i++) {
        int d = i * 32 + lane;
        s += xs[d] * gw[d * E_ + w];
    }
    #pragma unroll
    for (int o = 16; o; o >>= 1) s += __shfl_xor_sync(0xffffffffu, s, o);
    if (lane == 0) lg[w] = s;
    __syncthreads();
    if (threadIdx.x == 0) {
        int i0 = 0; float v0 = lg[0];
        #pragma unroll
        for (int e = 1; e < E_; e++) if (lg[e] > v0) { v0 = lg[e]; i0 = e; }
        int i1 = -1; float v1 = -1e30f;
        #pragma unroll
        for (int e = 0; e < E_; e++) if (e != i0 && lg[e] > v1) { v1 = lg[e]; i1 = e; }
        float ee = expf(v1 - v0);
        g_ce[t * 2 + 0] = i0; g_ce[t * 2 + 1] = i1;
        g_cw[t * 2 + 0] = 1.0f / (1.0f + ee);
        g_cw[t * 2 + 1] = ee / (1.0f + ee);
        float ssum = 0.0f, pe[E_];
        #pragma unroll
        for (int e = 0; e < E_; e++) { pe[e] = expf(lg[e] - v0); ssum += pe[e]; }
        float inv = 1.0f / ssum;
        #pragma unroll
        for (int e = 0; e < E_; e++) g_probs[t * E_ + e] = pe[e] * inv;
    }
}

__global__ void __launch_bounds__(256) k_count() {
    int b = blockIdx.x, i = threadIdx.x, t = b * 256 + i;
    __shared__ short se0[256], se1[256];
    __shared__ int cnt[E_];
    int e0 = g_ce[t * 2], e1 = g_ce[t * 2 + 1];
    se0[i] = (short)e0; se1[i] = (short)e1;
    if (i < E_) cnt[i] = 0;
    __syncthreads();
    int r0 = 0, r1 = 0;
    for (int j = 0; j < i; j++) {
        r0 += (se0[j] == e0) + (se1[j] == e0);
        r1 += (se0[j] == e1) + (se1[j] == e1);
    }
    g_rank[t * 2] = r0; g_rank[t * 2 + 1] = r1;
    atomicAdd(&cnt[e0], 1); atomicAdd(&cnt[e1], 1);
    __syncthreads();
    if (i < E_) g_blockcnt[b][i] = cnt[i];
}

__global__ void k_scan() {
    int e = threadIdx.x;
    if (e < E_) {
        int c = 0;
        #pragma unroll 8
        for (int b = 0; b < NBLK; b++) { g_blockbase[b][e] = c; c += g_blockcnt[b][e]; }
        g_cnt[e] = c;
    }
    __syncthreads();
    if (threadIdx.x == 0) {
        int poff = 0, np = 0;
        for (int ee = 0; ee < E_; ee++) {
            g_poff[ee] = poff;
            int nc = (g_cnt[ee] + CHROWS - 1) / CHROWS;
            g_chstart[ee] = np;
            g_chcnt[ee] = nc;
            for (int c = 0; c < nc; c++) {
                g_chunk_expert[np] = ee;
                g_chunk_row0[np] = poff + c * CHROWS;
                np++;
            }
            poff += nc * CHROWS;
        }
        g_poff[E_] = poff;
        g_nchunks = np;
    }
}

__global__ void __launch_bounds__(256) k_rows() {
    int t = blockIdx.x * 256 + threadIdx.x;
    int blk = blockIdx.x;
    #pragma unroll
    for (int k = 0; k < K_; k++) {
        int e = g_ce[t * 2 + k];
        int row = g_poff[e] + g_blockbase[blk][e] + g_rank[t * 2 + k];
        g_row_token[row] = t;
        g_row_w[row] = g_cw[t * 2 + k];
    }
}

__global__ void __launch_bounds__(256) k_gather(const float* __restrict__ x) {
    int padtot = g_poff[E_];
    for (int rr = 0; rr < 8; rr++) {
        int row = blockIdx.x * 8 + rr;
        if (row >= padtot) return;
        int e = 0;
        #pragma unroll
        for (int ee = 0; ee < E_ - 1; ee++) if (row >= g_poff[ee + 1]) e = ee + 1;
        int local = row - g_poff[e];
        float4* dst = (float4*)(g_yall + (size_t)row * D_);
        if (local < g_cnt[e]) {
            int t = g_row_token[row];
            float w = g_row_w[row];
            const float4* src = (const float4*)(x + (size_t)t * D_);
            for (int i = threadIdx.x; i < D_ / 4; i += 256) {
                float4 v = src[i];
                v.x = to_tf32(v.x * w); v.y = to_tf32(v.y * w);
                v.z = to_tf32(v.z * w); v.w = to_tf32(v.w * w);
                dst[i] = v;
            }
        } else {
            float4 z = {0.f, 0.f, 0.f, 0.f};
            for (int i = threadIdx.x; i < D_ / 4; i += 256) dst[i] = z;
        }
    }
}

// ---------------- tf32 mma.sync expert GEMM ----------------
// Block: 128 rows x 64 H-cols, gate+up. 8 warps = 4(M) x 2(N), warp 32x32.
// SMEM stage: As[128][36] + Gs[64][36] + Us[64][36] (pad 36 = conflict-free
// fragment LDS). Double-buffered via cp.async. Epilogue: silu(g)*u colsums.
#define STF   9216                 // floats per stage (4608+2304+2304)
#define STB   36864                // bytes per stage
#define GEMM_SMEM (2 * STB + 256 * 4)

__global__ void __launch_bounds__(256, 1) k_gemm() {
    int chunk = blockIdx.x;
    if (chunk >= g_nchunks) return;
    int h0 = blockIdx.y * 64;
    int e = g_chunk_expert[chunk];
    int row0 = g_chunk_row0[chunk];

    extern __shared__ float sm[];
    uint32_t sb = smem_u32(sm);
    int tid = threadIdx.x, wid = tid >> 5, lane = tid & 31;
    int wm = wid & 3, wn = wid >> 2;
    int g = lane >> 2, t = lane & 3;

    const float* Arow = g_yall + (size_t)row0 * D_;
    const float* G = g_wgt + ((size_t)e * H_ + h0) * D_;
    const float* U = g_wut + ((size_t)e * H_ + h0) * D_;

    float accG[2][4][4] = {};
    float accU[2][4][4] = {};

    #define LOAD_STAGE(kt, s) do {                                             \
        int kb = (kt) * 32;                                                    \
        uint32_t base = sb + (s) * STB;                                        \
        _Pragma("unroll")                                                      \
        for (int j = 0; j < 4; j++) {                                          \
            int lin = j * 256 + tid;                                           \
            int m = lin >> 3, k4 = lin & 7;                                    \
            cpa16(base + (uint32_t)(m * 36 + k4 * 4) * 4,                      \
                  Arow + (size_t)m * D_ + kb + k4 * 4);                        \
        }                                                                      \
        _Pragma("unroll")                                                      \
        for (int j = 0; j < 2; j++) {                                          \
            int lin = j * 256 + tid;                                           \
            int n = lin >> 3, k4 = lin & 7;                                    \
            uint32_t o = (uint32_t)(n * 36 + k4 * 4) * 4;                      \
            cpa16(base + 18432 + o, G + (size_t)n * D_ + kb + k4 * 4);         \
            cpa16(base + 27648 + o, U + (size_t)n * D_ + kb + k4 * 4);         \
        }                                                                      \
        CP_COMMIT();                                                           \
    } while (0)

    LOAD_STAGE(0, 0);
    CP_WAIT0();
    __syncthreads();

    for (int kt = 0; kt < 32; kt++) {
        int s = kt & 1;
        if (kt + 1 < 32) LOAD_STAGE(kt + 1, s ^ 1);

        const float* As = sm + s * STF;
        const float* Gs = As + 4608;
        const float* Us = Gs + 2304;

        #pragma unroll
        for (int kk = 0; kk < 4; kk++) {
            int k0 = kk * 8 + t;
            float a[2][4];
            #pragma unroll
            for (int mt = 0; mt < 2; mt++) {
                int rb = wm * 32 + mt * 16;
                a[mt][0] = As[(rb + g) * 36 + k0];
                a[mt][1] = As[(rb + g + 8) * 36 + k0];
                a[mt][2] = As[(rb + g) * 36 + k0 + 4];
                a[mt][3] = As[(rb + g + 8) * 36 + k0 + 4];
            }
            float bg[4][2], bu[4][2];
            #pragma unroll
            for (int nt = 0; nt < 4; nt++) {
                int cb = wn * 32 + nt * 8;
                bg[nt][0] = Gs[(cb + g) * 36 + k0];
                bg[nt][1] = Gs[(cb + g) * 36 + k0 + 4];
                bu[nt][0] = Us[(cb + g) * 36 + k0];
                bu[nt][1] = Us[(cb + g) * 36 + k0 + 4];
            }
            #pragma unroll
            for (int mt = 0; mt < 2; mt++)
                #pragma unroll
                for (int nt = 0; nt < 4; nt++) {
                    mma8(accG[mt][nt], a[mt], bg[nt]);
                    mma8(accU[mt][nt], a[mt], bu[nt]);
                }
        }
        if (kt + 1 < 32) {
            CP_WAIT0();
            __syncthreads();
        }
    }

    // ---- epilogue: silu(g)*u, column sums over the 128 chunk rows ----
    float cs0[4], cs1[4];
    #pragma unroll
    for (int nt = 0; nt < 4; nt++) {
        float s0 = 0.0f, s1 = 0.0f;
        #pragma unroll
        for (int mt = 0; mt < 2; mt++) {
            #pragma unroll
            for (int r = 0; r < 4; r++) {
                float gv = accG[mt][nt][r], uv = accU[mt][nt][r];
                float v = (gv / (1.0f + expf(-gv))) * uv;
                if (r & 1) s1 += v; else s0 += v;
            }
        }
        cs0[nt] = s0; cs1[nt] = s1;
    }
    #pragma unroll
    for (int off = 4; off <= 16; off <<= 1) {
        #pragma unroll
        for (int nt = 0; nt < 4; nt++) {
            cs0[nt] += __shfl_xor_sync(0xffffffffu, cs0[nt], off);
            cs1[nt] += __shfl_xor_sync(0xffffffffu, cs1[nt], off);
        }
    }
    float* ep = sm + 2 * STF;   // [4 wm][64 cols]
    __syncthreads();
    if (g == 0) {
        #pragma unroll
        for (int nt = 0; nt < 4; nt++) {
            ep[wm * 64 + wn * 32 + nt * 8 + 2 * t]     = cs0[nt];
            ep[wm * 64 + wn * 32 + nt * 8 + 2 * t + 1] = cs1[nt];
        }
    }
    __syncthreads();
    if (tid < 64) {
        float s = ep[tid] + ep[64 + tid] + ep[128 + tid] + ep[192 + tid];
        g_partial[(size_t)chunk * H_ + h0 + tid] = s;
    }
}

// ---------------- reductions + down-proj ----------------
__global__ void __launch_bounds__(256) k_colreduce() {
    int e = blockIdx.y;
    int h = blockIdx.x * 256 + threadIdx.x;
    int cs = g_chstart[e], cc = g_chcnt[e];
    float s = 0.0f;
    for (int c = 0; c < cc; c++) s += g_partial[(size_t)(cs + c) * H_ + h];
    g_acc[e * H_ + h] = s;
}

__global__ void __launch_bounds__(256) k_psum() {
    int e = blockIdx.x;
    __shared__ float sm2[256];
    float s = 0.0f;
    for (int t = threadIdx.x; t < T_; t += 256) s += g_probs[t * E_ + e];
    sm2[threadIdx.x] = s;
    __syncthreads();
    for (int st = 128; st > 0; st >>= 1) {
        if (threadIdx.x < st) sm2[threadIdx.x] += sm2[threadIdx.x + st];
        __syncthreads();
    }
    if (threadIdx.x == 0) g_psum[e] = sm2[0];
}

__global__ void __launch_bounds__(256) k_down(const float* __restrict__ wd,
                                              float* __restrict__ out,
                                              int out_size) {
    int e = blockIdx.y;
    int d = blockIdx.x * 256 + threadIdx.x;
    __shared__ float as[H_];
    for (int i = threadIdx.x; i < H_; i += 256) as[i] = g_acc[e * H_ + i];
    __syncthreads();
    const float* W = wd + (size_t)e * H_ * D_ + d;
    float s = 0.0f;
    #pragma unroll 8
    for (int h = 0; h < H_; h++) s += as[h] * W[(size_t)h * D_];
    out[e * D_ + d] = s;
    if (e == 0 && blockIdx.x == 0 && threadIdx.x == 0 && out_size > BSD) {
        float aux = 0.0f;
        #pragma unroll
        for (int ee = 0; ee < E_; ee++)
            aux += ((float)g_cnt[ee] / (float)T_) * (g_psum[ee] / (float)T_);
        out[BSD] = aux * (float)(E_ * E_);
    }
}

// ---------------- launch ----------------
extern "C" void kernel_launch(void* const* d_in, const int* in_sizes, int n_in,
                              void* d_out, int out_size) {
    const float* x  = (const float*)d_in[0];
    const float* gw = (const float*)d_in[1];
    const float* wg = (const float*)d_in[2];
    const float* wu = (const float*)d_in[3];
    const float* wd = (const float*)d_in[4];
    float* out = (float*)d_out;

    cudaFuncSetAttribute(k_gemm, cudaFuncAttributeMaxDynamicSharedMemorySize, GEMM_SMEM);

    k_zero<<<2048, 256>>>(out, out_size);
    dim3 gt(D_ / 32, H_ / 32, 2 * E_);
    k_transpose<<<gt, 256>>>(wg, wu);
    k_gate<<<T_, 256>>>(x, gw);
    k_count<<<NBLK, 256>>>();
    k_scan<<<1, 32>>>();
    k_rows<<<NBLK, 256>>>();
    k_gather<<<MAXROWS / 8, 256>>>(x);
    dim3 gg(MAXCH, H_ / 64);
    k_gemm<<<gg, 256, GEMM_SMEM>>>();
    dim3 gr(H_ / 256, E_);
    k_colreduce<<<gr, 256>>>();
    k_psum<<<E_, 256>>>();
    dim3 gd(D_ / 256, E_);
    k_down<<<gd, 256>>>(wd, out, out_size);
}